// round 3
// baseline (speedup 1.0000x reference)
#include <cuda_runtime.h>
#include <math.h>

constexpr int B_   = 256;
constexpr int Q_   = 512;
constexpr int D_   = 32;
constexpr int H_   = 192;
constexpr int HID_ = 384;
constexpr int INC_ = 96;     // 3*D
constexpr int BQ_  = B_ * Q_;
constexpr float PI_ = 3.14159265358979323846f;

// ------------------------- scratch (device globals) ------------------------
// NEVER passed from host: kernels reference these directly or via sel_buf().
__device__ float g_feats[(size_t)BQ_ * INC_];
__device__ float g_h   [(size_t)BQ_ * H_];
__device__ float g_y   [(size_t)BQ_ * H_];
__device__ float g_y1  [(size_t)BQ_ * HID_];
__device__ float g_gx  [B_ * HID_];
__device__ float g_scale[B_ * HID_];
__device__ float g_rp  [BQ_ * 2];
__device__ float g_gain[(size_t)BQ_ * D_];
__device__ float g_hr  [B_ * H_];
__device__ float g_curr[B_ * D_];
__device__ float g_x   [B_ * H_];
__device__ float g_gh  [B_ * 3 * H_];
__device__ float g_packA[224 * 768];   // [k][c]: c<192 -> roll_in_w, else whh (k>=192 zero)
__device__ float g_bA  [768];
__device__ float g_wihT[192 * 576];    // [k][o]

__device__ __forceinline__ const float* sel_buf(int s) {
    switch (s) {
        case 0:  return g_feats;
        case 1:  return g_h;
        case 2:  return g_y;
        default: return g_y1;
    }
}
__device__ __forceinline__ float* sel_buf_w(int s) {
    switch (s) {
        case 0:  return g_feats;
        case 1:  return g_h;
        case 2:  return g_y;
        default: return g_y1;
    }
}

__device__ __forceinline__ float sigf(float x) { return 1.0f / (1.0f + expf(-x)); }

__device__ __forceinline__ float warp_sum(float v) {
#pragma unroll
    for (int o = 16; o > 0; o >>= 1) v += __shfl_xor_sync(0xffffffffu, v, o);
    return v;
}

// ------------------------- features ----------------------------------------
__global__ void k_feats(const float* __restrict__ x_in) {
    int idx = blockIdx.x * blockDim.x + threadIdx.x;
    if (idx >= BQ_ * D_) return;
    int d   = idx & 31;
    int row = idx >> 5;
    int t   = row & (Q_ - 1);
    float xt  = x_in[(size_t)row * D_ + d];
    float xm1 = (t >= 1) ? x_in[(size_t)(row - 1) * D_ + d] : 0.0f;
    float xm2 = (t >= 2) ? x_in[(size_t)(row - 2) * D_ + d] : 0.0f;
    float dy   = (t >= 1) ? (xt - xm1) : 0.0f;
    float dym1 = (t >= 2) ? (xm1 - xm2) : 0.0f;
    float ddy  = (t >= 1) ? (dy - dym1) : 0.0f;
    size_t base = (size_t)row * INC_;
    g_feats[base + d]      = xt;
    g_feats[base + 32 + d] = dy;
    g_feats[base + 64 + d] = ddy;
}

// ------------------------- tiled SGEMM --------------------------------------
// C[row,n] = dot(A[row,:K], W[n,:K]) + bias[n] (+ epilogue per MODE)
// MODE 0: plain   MODE 1: exact GELU
// MODE 2: A' = A*g_scale[b]+grnb at load; += g_h residual at store
template <int MODE>
__global__ __launch_bounds__(256) void k_gemm(
    int a_sel, int c_sel,
    const float* __restrict__ W, const float* __restrict__ bias,
    int K, int N, const float* __restrict__ grnb)
{
    const float* A = sel_buf(a_sel);
    float*       C = sel_buf_w(c_sel);

    constexpr int BM = 128, BN = 64, BK = 16, TM = 8, TN = 4;
    constexpr int AS = 132, BS = 68;
    __shared__ float As[BK * AS];
    __shared__ float Bs[BK * BS];

    const int m0 = blockIdx.y * BM;
    const int n0 = blockIdx.x * BN;
    const int tid = threadIdx.x;
    const int tx = tid & 15;
    const int ty = tid >> 4;

    float acc[TM][TN];
#pragma unroll
    for (int i = 0; i < TM; i++)
#pragma unroll
        for (int j = 0; j < TN; j++) acc[i][j] = 0.0f;

    for (int k0 = 0; k0 < K; k0 += BK) {
#pragma unroll
        for (int it = 0; it < 2; it++) {
            int f = tid + it * 256;
            int row = f >> 2;
            int k4  = f & 3;
            int grow = m0 + row;
            int gk = k0 + k4 * 4;
            float4 v = *reinterpret_cast<const float4*>(A + (size_t)grow * K + gk);
            if (MODE == 2) {
                int b = grow >> 9;   // Q = 512
                float4 sc = *reinterpret_cast<const float4*>(g_scale + (size_t)b * HID_ + gk);
                float4 gb = *reinterpret_cast<const float4*>(grnb + gk);
                v.x = fmaf(v.x, sc.x, gb.x);
                v.y = fmaf(v.y, sc.y, gb.y);
                v.z = fmaf(v.z, sc.z, gb.z);
                v.w = fmaf(v.w, sc.w, gb.w);
            }
            As[(k4 * 4 + 0) * AS + row] = v.x;
            As[(k4 * 4 + 1) * AS + row] = v.y;
            As[(k4 * 4 + 2) * AS + row] = v.z;
            As[(k4 * 4 + 3) * AS + row] = v.w;
        }
        {
            int f = tid;
            int row = f >> 2;
            int k4  = f & 3;
            float4 v = *reinterpret_cast<const float4*>(W + (size_t)(n0 + row) * K + (k0 + k4 * 4));
            Bs[(k4 * 4 + 0) * BS + row] = v.x;
            Bs[(k4 * 4 + 1) * BS + row] = v.y;
            Bs[(k4 * 4 + 2) * BS + row] = v.z;
            Bs[(k4 * 4 + 3) * BS + row] = v.w;
        }
        __syncthreads();

#pragma unroll
        for (int kk = 0; kk < BK; kk++) {
            float a[TM], b[TN];
            const float4* a4 = reinterpret_cast<const float4*>(&As[kk * AS + ty * TM]);
            float4 av0 = a4[0], av1 = a4[1];
            a[0]=av0.x; a[1]=av0.y; a[2]=av0.z; a[3]=av0.w;
            a[4]=av1.x; a[5]=av1.y; a[6]=av1.z; a[7]=av1.w;
            float4 bv = *reinterpret_cast<const float4*>(&Bs[kk * BS + tx * TN]);
            b[0]=bv.x; b[1]=bv.y; b[2]=bv.z; b[3]=bv.w;
#pragma unroll
            for (int i = 0; i < TM; i++)
#pragma unroll
                for (int j = 0; j < TN; j++) acc[i][j] = fmaf(a[i], b[j], acc[i][j]);
        }
        __syncthreads();
    }

#pragma unroll
    for (int i = 0; i < TM; i++) {
        int row = m0 + ty * TM + i;
#pragma unroll
        for (int j = 0; j < TN; j++) {
            int n = n0 + tx * TN + j;
            float v = acc[i][j] + bias[n];
            if (MODE == 1) v = 0.5f * v * (1.0f + erff(v * 0.70710678118654752f));
            if (MODE == 2) v += g_h[(size_t)row * N + n];
            C[(size_t)row * N + n] = v;
        }
    }
}

// ------------------------- depthwise conv (K=9, edge pad) + channel LN ------
// reads g_h, writes g_y
__global__ __launch_bounds__(256) void k_conv(
    const float* __restrict__ dw_w, const float* __restrict__ dw_b,
    const float* __restrict__ ln_w, const float* __restrict__ ln_b)
{
    __shared__ float s_in[24][H_];
    __shared__ float s_out[16][H_];
    __shared__ float s_w[H_ * 9];
    __shared__ float s_b[H_];

    const int b  = blockIdx.y;
    const int t0 = blockIdx.x * 16;
    const int tid = threadIdx.x;

    for (int i = tid; i < H_ * 9; i += 256) s_w[i] = dw_w[i];
    for (int i = tid; i < H_; i += 256) s_b[i] = dw_b[i];
    for (int i = tid; i < 24 * H_; i += 256) {
        int r = i / H_, ch = i % H_;
        int t = t0 + r - 4;
        t = min(max(t, 0), Q_ - 1);
        s_in[r][ch] = g_h[((size_t)b * Q_ + t) * H_ + ch];
    }
    __syncthreads();

    for (int i = tid; i < 16 * H_; i += 256) {
        int r = i / H_, ch = i % H_;
        float acc = s_b[ch];
#pragma unroll
        for (int k = 0; k < 9; k++) acc = fmaf(s_in[r + k][ch], s_w[ch * 9 + k], acc);
        s_out[r][ch] = acc;
    }
    __syncthreads();

    const int wid = tid >> 5, lane = tid & 31;
#pragma unroll
    for (int rr = 0; rr < 2; rr++) {
        int r = wid * 2 + rr;
        float v[6], sum = 0.0f;
#pragma unroll
        for (int j = 0; j < 6; j++) { v[j] = s_out[r][j * 32 + lane]; sum += v[j]; }
        sum = warp_sum(sum);
        float mean = sum * (1.0f / H_);
        float var = 0.0f;
#pragma unroll
        for (int j = 0; j < 6; j++) { float d = v[j] - mean; var = fmaf(d, d, var); }
        var = warp_sum(var) * (1.0f / H_);
        float inv = rsqrtf(var + 1e-5f);
        size_t base = ((size_t)b * Q_ + t0 + r) * H_;
#pragma unroll
        for (int j = 0; j < 6; j++) {
            int ch = j * 32 + lane;
            g_y[base + ch] = (v[j] - mean) * inv * ln_w[ch] + ln_b[ch];
        }
    }
}

// ------------------------- GRN ----------------------------------------------
__global__ void k_grn1() {
    int b = blockIdx.y;
    int c = blockIdx.x * 128 + threadIdx.x;
    const float* p = g_y1 + (size_t)b * Q_ * HID_ + c;
    float acc = 0.0f;
#pragma unroll 8
    for (int t = 0; t < Q_; t++) {
        float v = p[(size_t)t * HID_];
        acc = fmaf(v, v, acc);
    }
    g_gx[b * HID_ + c] = sqrtf(acc);
}

__global__ void k_grn2(const float* __restrict__ grn_g) {
    __shared__ float red[HID_];
    int b = blockIdx.x, tid = threadIdx.x;
    float g = g_gx[b * HID_ + tid];
    red[tid] = g;
    __syncthreads();
    if (tid < 128) red[tid] += red[tid + 256];
    __syncthreads();
    for (int s = 128; s > 0; s >>= 1) {
        if (tid < s) red[tid] += red[tid + s];
        __syncthreads();
    }
    float mean = red[0] * (1.0f / HID_);
    float nx = g / (mean + 1e-6f);
    g_scale[b * HID_ + tid] = 1.0f + grn_g[tid] * nx;
}

// ------------------------- out-LN + rho/phi/gain -----------------------------
__global__ __launch_bounds__(256) void k_rpg(
    const float* __restrict__ out_ln_w, const float* __restrict__ out_ln_b,
    const float* __restrict__ fc_rp_w, const float* __restrict__ fc_rp_b,
    const float* __restrict__ fc_gain_w, const float* __restrict__ fc_gain_b)
{
    const int wid = threadIdx.x >> 5, lane = threadIdx.x & 31;
    const int row = blockIdx.x * 8 + wid;
    const float* hp = g_h + (size_t)row * H_;

    float v[6], sum = 0.0f;
#pragma unroll
    for (int j = 0; j < 6; j++) { v[j] = hp[j * 32 + lane]; sum += v[j]; }
    sum = warp_sum(sum);
    float mean = sum * (1.0f / H_);
    float var = 0.0f;
#pragma unroll
    for (int j = 0; j < 6; j++) { float d = v[j] - mean; var = fmaf(d, d, var); }
    var = warp_sum(var) * (1.0f / H_);
    float inv = rsqrtf(var + 1e-5f);

    float hn[6];
#pragma unroll
    for (int j = 0; j < 6; j++) {
        int ch = j * 32 + lane;
        hn[j] = (v[j] - mean) * inv * out_ln_w[ch] + out_ln_b[ch];
    }

    int t = row & (Q_ - 1), b = row >> 9;
    if (t == Q_ - 1) {
#pragma unroll
        for (int j = 0; j < 6; j++) g_hr[b * H_ + j * 32 + lane] = hn[j];
    }

#pragma unroll
    for (int o = 0; o < 2; o++) {
        float a = 0.0f;
#pragma unroll
        for (int j = 0; j < 6; j++) a = fmaf(hn[j], fc_rp_w[o * H_ + j * 32 + lane], a);
        a = warp_sum(a);
        if (lane == 0) {
            float z = a + fc_rp_b[o];
            g_rp[row * 2 + o] = (o == 0) ? 1.25f * sigf(z) : PI_ * tanhf(z);
        }
    }
    for (int d = 0; d < D_; d++) {
        float a = 0.0f;
#pragma unroll
        for (int j = 0; j < 6; j++) a = fmaf(hn[j], fc_gain_w[d * H_ + j * 32 + lane], a);
        a = warp_sum(a);
        if (lane == 0) g_gain[(size_t)row * D_ + d] = sigf(a + fc_gain_b[d]);
    }
}

// ------------------------- Kalman scan (1 warp per batch) --------------------
__global__ void k_scan(const float* __restrict__ x_in) {
    const int wid = threadIdx.x >> 5, lane = threadIdx.x & 31;
    const int b = blockIdx.x * 8 + wid;
    float x = x_in[((size_t)b * Q_) * D_ + lane];
    for (int t = 0; t < Q_; t++) {
        int idx = b * Q_ + t;
        float rho = g_rp[idx * 2];
        float phi = g_rp[idx * 2 + 1];
        float gn  = g_gain[(size_t)idx * D_ + lane];
        float y   = x_in[(size_t)idx * D_ + lane];
        float s, c;
        sincosf(phi, &s, &c);
        float partner = __shfl_xor_sync(0xffffffffu, x, 16);
        float xp = (lane < 16) ? rho * (c * x - s * partner)
                               : rho * (s * partner + c * x);
        x = xp + gn * (y - xp);
    }
    g_curr[b * D_ + lane] = x;
}

// ------------------------- rollout weight packing ----------------------------
__global__ void k_pack(const float* __restrict__ roll_in_w, const float* __restrict__ roll_in_b,
                       const float* __restrict__ gru_whh, const float* __restrict__ gru_bhh,
                       const float* __restrict__ gru_wih)
{
    int i = blockIdx.x * 256 + threadIdx.x;
    if (i < 224 * 768) {
        int k = i / 768, c = i % 768;
        float v;
        if (c < 192)      v = roll_in_w[c * 224 + k];
        else if (k < 192) v = gru_whh[(c - 192) * 192 + k];
        else              v = 0.0f;
        g_packA[i] = v;
    } else if (i < 224 * 768 + 768) {
        int c = i - 224 * 768;
        g_bA[c] = (c < 192) ? roll_in_b[c] : gru_bhh[c - 192];
    } else {
        int j = i - (224 * 768 + 768);
        if (j < 192 * 576) {
            int k = j / 576, o = j % 576;
            g_wihT[j] = gru_wih[o * 192 + k];
        }
    }
}

// ------------------------- rollout step A: x = tanh(...), gh ----------------
__global__ __launch_bounds__(256) void k_roll1() {
    __shared__ float sA[4][224];
    const int r0 = blockIdx.x * 4;
    const int tid = threadIdx.x;

    for (int i = tid; i < 4 * 224; i += 256) {
        int r = i / 224, k = i % 224;
        sA[r][k] = (k < 192) ? g_hr[(r0 + r) * H_ + k]
                             : g_curr[(r0 + r) * D_ + (k - 192)];
    }
    __syncthreads();

    float acc[3][4];
#pragma unroll
    for (int j = 0; j < 3; j++)
#pragma unroll
        for (int r = 0; r < 4; r++) acc[j][r] = 0.0f;

    for (int k = 0; k < 224; k++) {
        float a0 = sA[0][k], a1 = sA[1][k], a2 = sA[2][k], a3 = sA[3][k];
#pragma unroll
        for (int j = 0; j < 3; j++) {
            float w = g_packA[k * 768 + tid + j * 256];
            acc[j][0] = fmaf(a0, w, acc[j][0]);
            acc[j][1] = fmaf(a1, w, acc[j][1]);
            acc[j][2] = fmaf(a2, w, acc[j][2]);
            acc[j][3] = fmaf(a3, w, acc[j][3]);
        }
    }

#pragma unroll
    for (int j = 0; j < 3; j++) {
        int c = tid + j * 256;
        float bia = g_bA[c];
#pragma unroll
        for (int r = 0; r < 4; r++) {
            float v = acc[j][r] + bia;
            if (c < 192) g_x[(r0 + r) * H_ + c] = tanhf(v);
            else         g_gh[(r0 + r) * 3 * H_ + (c - 192)] = v;
        }
    }
}

// ------------------------- rollout step B: gi + gates + LN + rotate ---------
__global__ __launch_bounds__(192) void k_roll2(
    const float* __restrict__ gru_bih,
    const float* __restrict__ roll_ln_w, const float* __restrict__ roll_ln_b,
    const float* __restrict__ fc_rp_r_w, const float* __restrict__ fc_rp_r_b,
    float* __restrict__ out, int w_out, int step)
{
    __shared__ float sx[4][H_];
    __shared__ float sgi[4][3 * H_];
    __shared__ float spre[4][H_];

    const int r0 = blockIdx.x * 4;
    const int tid = threadIdx.x;

    for (int i = tid; i < 4 * H_; i += 192)
        sx[i / H_][i % H_] = g_x[(r0 + i / H_) * H_ + (i % H_)];
    __syncthreads();

    float acc[3][4];
#pragma unroll
    for (int j = 0; j < 3; j++)
#pragma unroll
        for (int r = 0; r < 4; r++) acc[j][r] = 0.0f;

    for (int k = 0; k < 192; k++) {
        float a0 = sx[0][k], a1 = sx[1][k], a2 = sx[2][k], a3 = sx[3][k];
#pragma unroll
        for (int j = 0; j < 3; j++) {
            float w = g_wihT[k * 576 + tid + j * 192];
            acc[j][0] = fmaf(a0, w, acc[j][0]);
            acc[j][1] = fmaf(a1, w, acc[j][1]);
            acc[j][2] = fmaf(a2, w, acc[j][2]);
            acc[j][3] = fmaf(a3, w, acc[j][3]);
        }
    }
#pragma unroll
    for (int j = 0; j < 3; j++) {
        int o = tid + j * 192;
        float bia = gru_bih[o];
#pragma unroll
        for (int r = 0; r < 4; r++) sgi[r][o] = acc[j][r] + bia;
    }
    __syncthreads();

#pragma unroll
    for (int ii = 0; ii < 4; ii++) {
        int idx = tid + ii * 192;
        int r = idx / H_, ch = idx % H_;
        int row = r0 + r;
        float gir = sgi[r][ch], giz = sgi[r][H_ + ch], gin = sgi[r][2 * H_ + ch];
        float ghr = g_gh[row * 3 * H_ + ch];
        float ghz = g_gh[row * 3 * H_ + H_ + ch];
        float ghn = g_gh[row * 3 * H_ + 2 * H_ + ch];
        float rg = sigf(gir + ghr);
        float zg = sigf(giz + ghz);
        float ng = tanhf(gin + rg * ghn);
        float hr = g_hr[row * H_ + ch];
        spre[r][ch] = (1.0f - zg) * ng + zg * hr;
    }
    __syncthreads();

    const int wid = tid >> 5, lane = tid & 31;
    if (wid < 4) {
        int r = wid, row = r0 + r;
        float v[6], sum = 0.0f;
#pragma unroll
        for (int j = 0; j < 6; j++) { v[j] = spre[r][j * 32 + lane]; sum += v[j]; }
        sum = warp_sum(sum);
        float mean = sum * (1.0f / H_);
        float var = 0.0f;
#pragma unroll
        for (int j = 0; j < 6; j++) { float d = v[j] - mean; var = fmaf(d, d, var); }
        var = warp_sum(var) * (1.0f / H_);
        float inv = rsqrtf(var + 1e-5f);

        float p0 = 0.0f, p1 = 0.0f;
#pragma unroll
        for (int j = 0; j < 6; j++) {
            int ch = j * 32 + lane;
            float hn = (v[j] - mean) * inv * roll_ln_w[ch] + roll_ln_b[ch];
            g_hr[row * H_ + ch] = hn;
            p0 = fmaf(hn, fc_rp_r_w[ch], p0);
            p1 = fmaf(hn, fc_rp_r_w[H_ + ch], p1);
        }
        p0 = warp_sum(p0);
        p1 = warp_sum(p1);
        float rho = 1.25f * sigf(p0 + fc_rp_r_b[0]);
        float phi = PI_ * tanhf(p1 + fc_rp_r_b[1]);
        float s, c;
        sincosf(phi, &s, &c);
        float cur = g_curr[row * D_ + lane];
        float partner = __shfl_xor_sync(0xffffffffu, cur, 16);
        float nv = (lane < 16) ? rho * (c * cur - s * partner)
                               : rho * (s * partner + c * cur);
        g_curr[row * D_ + lane] = nv;
        out[((size_t)row * w_out + step) * D_ + lane] = nv;
    }
}

// -----------------------------------------------------------------------------
extern "C" void kernel_launch(void* const* d_in, const int* in_sizes, int n_in,
                              void* d_out, int out_size) {
    const float* x_in      = (const float*)d_in[0];
    const float* inp_w     = (const float*)d_in[1];
    const float* inp_b     = (const float*)d_in[2];
    const float* b_dw_w    = (const float*)d_in[3];
    const float* b_dw_b    = (const float*)d_in[4];
    const float* b_ln_w    = (const float*)d_in[5];
    const float* b_ln_b    = (const float*)d_in[6];
    const float* b_pw1_w   = (const float*)d_in[7];
    const float* b_pw1_b   = (const float*)d_in[8];
    const float* b_grn_g   = (const float*)d_in[9];
    const float* b_grn_b   = (const float*)d_in[10];
    const float* b_pw2_w   = (const float*)d_in[11];
    const float* b_pw2_b   = (const float*)d_in[12];
    const float* out_ln_w  = (const float*)d_in[13];
    const float* out_ln_b  = (const float*)d_in[14];
    const float* fc_rp_w   = (const float*)d_in[15];
    const float* fc_rp_b   = (const float*)d_in[16];
    const float* fc_gain_w = (const float*)d_in[17];
    const float* fc_gain_b = (const float*)d_in[18];
    const float* roll_in_w = (const float*)d_in[19];
    const float* roll_in_b = (const float*)d_in[20];
    const float* gru_wih   = (const float*)d_in[21];
    const float* gru_whh   = (const float*)d_in[22];
    const float* gru_bih   = (const float*)d_in[23];
    const float* gru_bhh   = (const float*)d_in[24];
    const float* roll_ln_w = (const float*)d_in[25];
    const float* roll_ln_b = (const float*)d_in[26];
    const float* fc_rp_r_w = (const float*)d_in[27];
    const float* fc_rp_r_b = (const float*)d_in[28];

    float* out = (float*)d_out;
    const int w_out = out_size / (B_ * D_);

    // 1. features
    k_feats<<<(BQ_ * D_ + 255) / 256, 256>>>(x_in);

    // 2. input projection: g_feats(0) -> g_h(1)
    {
        dim3 grid(H_ / 64, BQ_ / 128);
        k_gemm<0><<<grid, 256>>>(0, 1, inp_w, inp_b, INC_, H_, nullptr);
    }

    // 3. ConvNeXt blocks
    for (int blk = 0; blk < 2; blk++) {
        {
            dim3 grid(Q_ / 16, B_);
            k_conv<<<grid, 256>>>(b_dw_w + blk * H_ * 9, b_dw_b + blk * H_,
                                  b_ln_w + blk * H_,     b_ln_b + blk * H_);
        }
        {
            // pw1 + GELU: g_y(2) -> g_y1(3)
            dim3 grid(HID_ / 64, BQ_ / 128);
            k_gemm<1><<<grid, 256>>>(2, 3, b_pw1_w + blk * HID_ * H_,
                                     b_pw1_b + blk * HID_, H_, HID_, nullptr);
        }
        {
            dim3 grid(HID_ / 128, B_);
            k_grn1<<<grid, 128>>>();
            k_grn2<<<B_, HID_>>>(b_grn_g + blk * HID_);
        }
        {
            // pw2 + GRN-on-load + residual: g_y1(3) -> g_h(1)
            dim3 grid(H_ / 64, BQ_ / 128);
            k_gemm<2><<<grid, 256>>>(3, 1, b_pw2_w + blk * H_ * HID_,
                                     b_pw2_b + blk * H_, HID_, H_,
                                     b_grn_b + blk * HID_);
        }
    }

    // 4. out-LN + rho/phi/gain (+ capture h_seq[:, -1, :])
    k_rpg<<<BQ_ / 8, 256>>>(out_ln_w, out_ln_b, fc_rp_w, fc_rp_b,
                            fc_gain_w, fc_gain_b);

    // 5. Kalman scan -> g_curr
    k_scan<<<B_ / 8, 256>>>(x_in);

    // 6. pack rollout weights
    k_pack<<<(224 * 768 + 768 + 192 * 576 + 255) / 256, 256>>>(
        roll_in_w, roll_in_b, gru_whh, gru_bhh, gru_wih);

    // 7. GRU rollout
    for (int step = 0; step < w_out; step++) {
        k_roll1<<<B_ / 4, 256>>>();
        k_roll2<<<B_ / 4, 192>>>(gru_bih, roll_ln_w, roll_ln_b,
                                 fc_rp_r_w, fc_rp_r_b, out, w_out, step);
    }
}

// round 4
// speedup vs baseline: 1.1687x; 1.1687x over previous
#include <cuda_runtime.h>
#include <math.h>

constexpr int B_   = 256;
constexpr int Q_   = 512;
constexpr int D_   = 32;
constexpr int H_   = 192;
constexpr int HID_ = 384;
constexpr int INC_ = 96;     // 3*D
constexpr int BQ_  = B_ * Q_;
constexpr float PI_ = 3.14159265358979323846f;

typedef unsigned long long ull;

// ------------------------- scratch (device globals) ------------------------
__device__ float g_h   [(size_t)BQ_ * H_];
__device__ float g_y   [(size_t)BQ_ * H_];
__device__ float g_y1  [(size_t)BQ_ * HID_];
__device__ float g_part[2 * B_ * HID_];     // GRN partial sums-of-squares (2 half-tiles per batch)
__device__ float g_scale[B_ * HID_];
__device__ float g_rp  [BQ_ * 2];
__device__ float g_gain[(size_t)BQ_ * D_];
__device__ float g_hr  [B_ * H_];
__device__ float g_curr[B_ * D_];
__device__ float g_packA[224 * 768];        // [k][c]: c<192 -> roll_in_w, else whh (k>=192 zero)
__device__ float g_bA  [768];
__device__ float g_wihT[192 * 576];         // [k][o]

__device__ __forceinline__ const float* sel_buf(int s) {
    switch (s) {
        case 1:  return g_h;
        case 2:  return g_y;
        default: return g_y1;
    }
}
__device__ __forceinline__ float* sel_buf_w(int s) {
    switch (s) {
        case 1:  return g_h;
        case 2:  return g_y;
        default: return g_y1;
    }
}

__device__ __forceinline__ float sigf(float x) { return 1.0f / (1.0f + expf(-x)); }

__device__ __forceinline__ float warp_sum(float v) {
#pragma unroll
    for (int o = 16; o > 0; o >>= 1) v += __shfl_xor_sync(0xffffffffu, v, o);
    return v;
}

// packed f32x2 helpers (sm_103a)
__device__ __forceinline__ ull ff2(ull a, ull b, ull c) {
    ull d;
    asm("fma.rn.f32x2 %0, %1, %2, %3;" : "=l"(d) : "l"(a), "l"(b), "l"(c));
    return d;
}
__device__ __forceinline__ ull dup2(float x) {
    ull d;
    unsigned xb = __float_as_uint(x);
    asm("mov.b64 %0, {%1, %1};" : "=l"(d) : "r"(xb));
    return d;
}
__device__ __forceinline__ float lo2(ull v) { return __uint_as_float((unsigned)v); }
__device__ __forceinline__ float hi2(ull v) { return __uint_as_float((unsigned)(v >> 32)); }

// ------------------------- tiled SGEMM (256x64, f32x2) ----------------------
// C[row,n] = dot(A[row,:K], W[n,:K]) + bias[n]
// MODE 1: GELU epilogue + GRN partial sum-of-squares (requires N == HID_)
// MODE 2: A' = A*g_scale[b] + grnb at load; += g_h residual at store
// MODE 3: A synthesized on the fly from x_in (features), K = 96
template <int MODE>
__global__ __launch_bounds__(256, 2) void k_gemm(
    int a_sel, int c_sel,
    const float* __restrict__ W, const float* __restrict__ bias,
    int K, int N, const float* __restrict__ grnb,
    const float* __restrict__ x_in)
{
    constexpr int BM = 256, BN = 64, BK = 16;
    constexpr int AS = 260, BS = 68;
    __shared__ float As[BK * AS];
    __shared__ float Bs[BK * BS];

    const float* A = (MODE == 3) ? (const float*)0 : sel_buf(a_sel);
    float*       C = sel_buf_w(c_sel);

    const int m0 = blockIdx.y * BM;
    const int n0 = blockIdx.x * BN;
    const int tid = threadIdx.x;
    const int tx = tid & 15;      // 16 col groups * 4 cols
    const int ty = tid >> 4;      // 16 row groups * 16 rows

    ull acc[8][4];
#pragma unroll
    for (int p = 0; p < 8; p++)
#pragma unroll
        for (int j = 0; j < 4; j++) acc[p][j] = 0ull;

    for (int k0 = 0; k0 < K; k0 += BK) {
        // ---- A tile: 256 rows x 16 k, 4 float4 per thread ----
#pragma unroll
        for (int it = 0; it < 4; it++) {
            int f = tid + it * 256;
            int row = f >> 2;
            int k4  = f & 3;
            int grow = m0 + row;
            int gk = k0 + k4 * 4;
            float4 v;
            if (MODE == 3) {
                int t = grow & (Q_ - 1);
                int g = gk >> 5;           // 0:x  1:dy  2:ddy
                int d = gk & 31;
                const float* xr = x_in + (size_t)grow * D_ + d;
                float4 x0 = *reinterpret_cast<const float4*>(xr);
                if (g == 0) {
                    v = x0;
                } else {
                    float4 x1 = (t >= 1) ? *reinterpret_cast<const float4*>(xr - D_) : x0;
                    if (g == 1) {
                        v = make_float4(x0.x - x1.x, x0.y - x1.y, x0.z - x1.z, x0.w - x1.w);
                    } else {
                        float4 x2 = (t >= 2) ? *reinterpret_cast<const float4*>(xr - 2 * D_) : x1;
                        v = make_float4(x0.x - 2.0f * x1.x + x2.x,
                                        x0.y - 2.0f * x1.y + x2.y,
                                        x0.z - 2.0f * x1.z + x2.z,
                                        x0.w - 2.0f * x1.w + x2.w);
                    }
                }
            } else {
                v = *reinterpret_cast<const float4*>(A + (size_t)grow * K + gk);
                if (MODE == 2) {
                    int b = grow >> 9;   // Q = 512
                    float4 sc = *reinterpret_cast<const float4*>(g_scale + (size_t)b * HID_ + gk);
                    float4 gb = *reinterpret_cast<const float4*>(grnb + gk);
                    v.x = fmaf(v.x, sc.x, gb.x);
                    v.y = fmaf(v.y, sc.y, gb.y);
                    v.z = fmaf(v.z, sc.z, gb.z);
                    v.w = fmaf(v.w, sc.w, gb.w);
                }
            }
            As[(k4 * 4 + 0) * AS + row] = v.x;
            As[(k4 * 4 + 1) * AS + row] = v.y;
            As[(k4 * 4 + 2) * AS + row] = v.z;
            As[(k4 * 4 + 3) * AS + row] = v.w;
        }
        // ---- B tile: 64 n x 16 k, 1 float4 per thread ----
        {
            int row = tid >> 2;
            int k4  = tid & 3;
            float4 v = *reinterpret_cast<const float4*>(W + (size_t)(n0 + row) * K + (k0 + k4 * 4));
            Bs[(k4 * 4 + 0) * BS + row] = v.x;
            Bs[(k4 * 4 + 1) * BS + row] = v.y;
            Bs[(k4 * 4 + 2) * BS + row] = v.z;
            Bs[(k4 * 4 + 3) * BS + row] = v.w;
        }
        __syncthreads();

#pragma unroll
        for (int kk = 0; kk < BK; kk++) {
            // 16 A values = 8 packed row-pairs, loaded directly as 64-bit
            const ulonglong2* a2 = reinterpret_cast<const ulonglong2*>(&As[kk * AS + ty * 16]);
            ulonglong2 q0 = a2[0], q1 = a2[1], q2 = a2[2], q3 = a2[3];
            ull ap[8];
            ap[0] = q0.x; ap[1] = q0.y; ap[2] = q1.x; ap[3] = q1.y;
            ap[4] = q2.x; ap[5] = q2.y; ap[6] = q3.x; ap[7] = q3.y;
            float4 bv = *reinterpret_cast<const float4*>(&Bs[kk * BS + tx * 4]);
            ull bd[4];
            bd[0] = dup2(bv.x); bd[1] = dup2(bv.y); bd[2] = dup2(bv.z); bd[3] = dup2(bv.w);
#pragma unroll
            for (int p = 0; p < 8; p++)
#pragma unroll
                for (int j = 0; j < 4; j++)
                    acc[p][j] = ff2(ap[p], bd[j], acc[p][j]);
        }
        __syncthreads();
    }

    // ---- epilogue ----
    float4 bia = *reinterpret_cast<const float4*>(bias + n0 + tx * 4);
    float vv[4] = {0.0f, 0.0f, 0.0f, 0.0f};

#pragma unroll
    for (int p = 0; p < 8; p++) {
#pragma unroll
        for (int hf = 0; hf < 2; hf++) {
            int row = m0 + ty * 16 + p * 2 + hf;
            float v0 = (hf ? hi2(acc[p][0]) : lo2(acc[p][0])) + bia.x;
            float v1 = (hf ? hi2(acc[p][1]) : lo2(acc[p][1])) + bia.y;
            float v2 = (hf ? hi2(acc[p][2]) : lo2(acc[p][2])) + bia.z;
            float v3 = (hf ? hi2(acc[p][3]) : lo2(acc[p][3])) + bia.w;
            if (MODE == 1) {
                v0 = 0.5f * v0 * (1.0f + erff(v0 * 0.70710678118654752f));
                v1 = 0.5f * v1 * (1.0f + erff(v1 * 0.70710678118654752f));
                v2 = 0.5f * v2 * (1.0f + erff(v2 * 0.70710678118654752f));
                v3 = 0.5f * v3 * (1.0f + erff(v3 * 0.70710678118654752f));
                vv[0] = fmaf(v0, v0, vv[0]);
                vv[1] = fmaf(v1, v1, vv[1]);
                vv[2] = fmaf(v2, v2, vv[2]);
                vv[3] = fmaf(v3, v3, vv[3]);
            }
            if (MODE == 2) {
                float4 r = *reinterpret_cast<const float4*>(g_h + (size_t)row * N + n0 + tx * 4);
                v0 += r.x; v1 += r.y; v2 += r.z; v3 += r.w;
            }
            float4 o4 = make_float4(v0, v1, v2, v3);
            *reinterpret_cast<float4*>(C + (size_t)row * N + n0 + tx * 4) = o4;
        }
    }

    if (MODE == 1) {
        // deterministic GRN partials: reduce vv over ty, per column
        float* sred = As;   // reuse (64 cols x 16)
        __syncthreads();
#pragma unroll
        for (int j = 0; j < 4; j++) sred[(tx * 4 + j) * 16 + ty] = vv[j];
        __syncthreads();
        if (tid < 64) {
            float s = 0.0f;
#pragma unroll
            for (int q = 0; q < 16; q++) s += sred[tid * 16 + q];
            int b = m0 >> 9;
            int half = (m0 >> 8) & 1;
            g_part[(half * B_ + b) * HID_ + n0 + tid] = s;
        }
    }
}

// ------------------------- depthwise conv (K=9, edge pad) + channel LN ------
__global__ __launch_bounds__(256) void k_conv(
    const float* __restrict__ dw_w, const float* __restrict__ dw_b,
    const float* __restrict__ ln_w, const float* __restrict__ ln_b)
{
    __shared__ float s_in[24][H_];
    __shared__ float s_out[16][H_];
    __shared__ float s_w[H_ * 9];
    __shared__ float s_b[H_];

    const int b  = blockIdx.y;
    const int t0 = blockIdx.x * 16;
    const int tid = threadIdx.x;

    for (int i = tid; i < H_ * 9; i += 256) s_w[i] = dw_w[i];
    for (int i = tid; i < H_; i += 256) s_b[i] = dw_b[i];
    for (int i = tid; i < 24 * H_; i += 256) {
        int r = i / H_, ch = i % H_;
        int t = t0 + r - 4;
        t = min(max(t, 0), Q_ - 1);
        s_in[r][ch] = g_h[((size_t)b * Q_ + t) * H_ + ch];
    }
    __syncthreads();

    for (int i = tid; i < 16 * H_; i += 256) {
        int r = i / H_, ch = i % H_;
        float acc = s_b[ch];
#pragma unroll
        for (int k = 0; k < 9; k++) acc = fmaf(s_in[r + k][ch], s_w[ch * 9 + k], acc);
        s_out[r][ch] = acc;
    }
    __syncthreads();

    const int wid = tid >> 5, lane = tid & 31;
#pragma unroll
    for (int rr = 0; rr < 2; rr++) {
        int r = wid * 2 + rr;
        float v[6], sum = 0.0f;
#pragma unroll
        for (int j = 0; j < 6; j++) { v[j] = s_out[r][j * 32 + lane]; sum += v[j]; }
        sum = warp_sum(sum);
        float mean = sum * (1.0f / H_);
        float var = 0.0f;
#pragma unroll
        for (int j = 0; j < 6; j++) { float d = v[j] - mean; var = fmaf(d, d, var); }
        var = warp_sum(var) * (1.0f / H_);
        float inv = rsqrtf(var + 1e-5f);
        size_t base = ((size_t)b * Q_ + t0 + r) * H_;
#pragma unroll
        for (int j = 0; j < 6; j++) {
            int ch = j * 32 + lane;
            g_y[base + ch] = (v[j] - mean) * inv * ln_w[ch] + ln_b[ch];
        }
    }
}

// ------------------------- GRN scale from partials ---------------------------
__global__ void k_grn2(const float* __restrict__ grn_g) {
    __shared__ float red[HID_];
    int b = blockIdx.x, tid = threadIdx.x;
    float g = sqrtf(g_part[b * HID_ + tid] + g_part[(B_ + b) * HID_ + tid]);
    red[tid] = g;
    __syncthreads();
    if (tid < 128) red[tid] += red[tid + 256];
    __syncthreads();
    for (int s = 128; s > 0; s >>= 1) {
        if (tid < s) red[tid] += red[tid + s];
        __syncthreads();
    }
    float mean = red[0] * (1.0f / HID_);
    float nx = g / (mean + 1e-6f);
    g_scale[b * HID_ + tid] = 1.0f + grn_g[tid] * nx;
}

// ------------------------- out-LN + rho/phi/gain -----------------------------
__global__ __launch_bounds__(256) void k_rpg(
    const float* __restrict__ out_ln_w, const float* __restrict__ out_ln_b,
    const float* __restrict__ fc_rp_w, const float* __restrict__ fc_rp_b,
    const float* __restrict__ fc_gain_w, const float* __restrict__ fc_gain_b)
{
    const int wid = threadIdx.x >> 5, lane = threadIdx.x & 31;
    const int row = blockIdx.x * 8 + wid;
    const float* hp = g_h + (size_t)row * H_;

    float v[6], sum = 0.0f;
#pragma unroll
    for (int j = 0; j < 6; j++) { v[j] = hp[j * 32 + lane]; sum += v[j]; }
    sum = warp_sum(sum);
    float mean = sum * (1.0f / H_);
    float var = 0.0f;
#pragma unroll
    for (int j = 0; j < 6; j++) { float d = v[j] - mean; var = fmaf(d, d, var); }
    var = warp_sum(var) * (1.0f / H_);
    float inv = rsqrtf(var + 1e-5f);

    float hn[6];
#pragma unroll
    for (int j = 0; j < 6; j++) {
        int ch = j * 32 + lane;
        hn[j] = (v[j] - mean) * inv * out_ln_w[ch] + out_ln_b[ch];
    }

    int t = row & (Q_ - 1), b = row >> 9;
    if (t == Q_ - 1) {
#pragma unroll
        for (int j = 0; j < 6; j++) g_hr[b * H_ + j * 32 + lane] = hn[j];
    }

#pragma unroll
    for (int o = 0; o < 2; o++) {
        float a = 0.0f;
#pragma unroll
        for (int j = 0; j < 6; j++) a = fmaf(hn[j], fc_rp_w[o * H_ + j * 32 + lane], a);
        a = warp_sum(a);
        if (lane == 0) {
            float z = a + fc_rp_b[o];
            g_rp[row * 2 + o] = (o == 0) ? 1.25f * sigf(z) : PI_ * tanhf(z);
        }
    }
    for (int d = 0; d < D_; d++) {
        float a = 0.0f;
#pragma unroll
        for (int j = 0; j < 6; j++) a = fmaf(hn[j], fc_gain_w[d * H_ + j * 32 + lane], a);
        a = warp_sum(a);
        if (lane == 0) g_gain[(size_t)row * D_ + d] = sigf(a + fc_gain_b[d]);
    }
}

// ------------------------- Kalman scan (1 warp per batch, prefetched) --------
__global__ void k_scan(const float* __restrict__ x_in) {
    const int wid = threadIdx.x >> 5, lane = threadIdx.x & 31;
    const int b = blockIdx.x * 8 + wid;
    const int base = b * Q_;

    float x  = x_in[(size_t)base * D_ + lane];
    float2 rp = *reinterpret_cast<const float2*>(g_rp + base * 2);
    float gn = g_gain[(size_t)base * D_ + lane];
    float y  = x;   // t=0 observation

    for (int t = 0; t < Q_; t++) {
        float2 rp_n = rp; float gn_n = gn, y_n = y;
        if (t + 1 < Q_) {
            rp_n = *reinterpret_cast<const float2*>(g_rp + (base + t + 1) * 2);
            gn_n = g_gain[(size_t)(base + t + 1) * D_ + lane];
            y_n  = x_in[(size_t)(base + t + 1) * D_ + lane];
        }
        float s, c;
        sincosf(rp.y, &s, &c);
        float partner = __shfl_xor_sync(0xffffffffu, x, 16);
        float xp = (lane < 16) ? rp.x * (c * x - s * partner)
                               : rp.x * (s * partner + c * x);
        x = xp + gn * (y - xp);
        rp = rp_n; gn = gn_n; y = y_n;
    }
    g_curr[b * D_ + lane] = x;
}

// ------------------------- rollout weight packing ----------------------------
__global__ void k_pack(const float* __restrict__ roll_in_w, const float* __restrict__ roll_in_b,
                       const float* __restrict__ gru_whh, const float* __restrict__ gru_bhh,
                       const float* __restrict__ gru_wih)
{
    int i = blockIdx.x * 256 + threadIdx.x;
    if (i < 224 * 768) {
        int k = i / 768, c = i % 768;
        float v;
        if (c < 192)      v = roll_in_w[c * 224 + k];
        else if (k < 192) v = gru_whh[(c - 192) * 192 + k];
        else              v = 0.0f;
        g_packA[i] = v;
    } else if (i < 224 * 768 + 768) {
        int c = i - 224 * 768;
        g_bA[c] = (c < 192) ? roll_in_b[c] : gru_bhh[c - 192];
    } else {
        int j = i - (224 * 768 + 768);
        if (j < 192 * 576) {
            int k = j / 576, o = j % 576;
            g_wihT[j] = gru_wih[o * 192 + k];
        }
    }
}

// ------------------------- persistent GRU rollout ----------------------------
// 64 blocks x 256 threads; each block owns 4 batches through ALL w_out steps.
// State (h_r | curr) lives in smem, transposed [k][4] so row-pairs load as u64.
__global__ __launch_bounds__(256) void k_roll(
    const float* __restrict__ gru_bih,
    const float* __restrict__ roll_ln_w, const float* __restrict__ roll_ln_b,
    const float* __restrict__ fc_rp_r_w, const float* __restrict__ fc_rp_r_b,
    float* __restrict__ out, int w_out)
{
    __shared__ float sSt[224][4];    // [k][r]: k<192 -> h_r, else curr
    __shared__ float sx [192][4];    // tanh output, transposed
    __shared__ float sgh[4][576];
    __shared__ float sgi[4][576];
    __shared__ float spre[4][192];

    const int r0 = blockIdx.x * 4;
    const int tid = threadIdx.x;
    const int wid = tid >> 5, lane = tid & 31;

    for (int i = tid; i < 4 * 224; i += 256) {
        int r = i / 224, k = i % 224;
        sSt[k][r] = (k < 192) ? g_hr[(r0 + r) * H_ + k]
                              : g_curr[(r0 + r) * D_ + (k - 192)];
    }
    __syncthreads();

    for (int step = 0; step < w_out; step++) {
        // ---- phase A: [x | gh] = [hr|curr] @ packA + bA ----
        {
            ull a01[3], a23[3];
#pragma unroll
            for (int j = 0; j < 3; j++) { a01[j] = 0ull; a23[j] = 0ull; }
            for (int k = 0; k < 224; k++) {
                ull p01 = *reinterpret_cast<const ull*>(&sSt[k][0]);
                ull p23 = *reinterpret_cast<const ull*>(&sSt[k][2]);
                const float* wp = g_packA + k * 768 + tid;
                ull w0 = dup2(wp[0]);
                ull w1 = dup2(wp[256]);
                ull w2 = dup2(wp[512]);
                a01[0] = ff2(p01, w0, a01[0]); a23[0] = ff2(p23, w0, a23[0]);
                a01[1] = ff2(p01, w1, a01[1]); a23[1] = ff2(p23, w1, a23[1]);
                a01[2] = ff2(p01, w2, a01[2]); a23[2] = ff2(p23, w2, a23[2]);
            }
#pragma unroll
            for (int j = 0; j < 3; j++) {
                int c = tid + j * 256;
                float bia = g_bA[c];
                float v0 = lo2(a01[j]) + bia;
                float v1 = hi2(a01[j]) + bia;
                float v2 = lo2(a23[j]) + bia;
                float v3 = hi2(a23[j]) + bia;
                if (c < 192) {
                    sx[c][0] = tanhf(v0); sx[c][1] = tanhf(v1);
                    sx[c][2] = tanhf(v2); sx[c][3] = tanhf(v3);
                } else {
                    int o = c - 192;
                    sgh[0][o] = v0; sgh[1][o] = v1; sgh[2][o] = v2; sgh[3][o] = v3;
                }
            }
        }
        __syncthreads();

        // ---- phase B1: gi = x @ wihT + bih ----
        {
            ull a01[3], a23[3];
#pragma unroll
            for (int j = 0; j < 3; j++) { a01[j] = 0ull; a23[j] = 0ull; }
            int o2c = (tid < 64) ? (tid + 512) : 575;   // clamp (result discarded)
            for (int k = 0; k < 192; k++) {
                ull p01 = *reinterpret_cast<const ull*>(&sx[k][0]);
                ull p23 = *reinterpret_cast<const ull*>(&sx[k][2]);
                const float* wp = g_wihT + k * 576;
                ull w0 = dup2(wp[tid]);
                ull w1 = dup2(wp[tid + 256]);
                ull w2 = dup2(wp[o2c]);
                a01[0] = ff2(p01, w0, a01[0]); a23[0] = ff2(p23, w0, a23[0]);
                a01[1] = ff2(p01, w1, a01[1]); a23[1] = ff2(p23, w1, a23[1]);
                a01[2] = ff2(p01, w2, a01[2]); a23[2] = ff2(p23, w2, a23[2]);
            }
#pragma unroll
            for (int j = 0; j < 3; j++) {
                int o = tid + j * 256;
                if (o < 576) {
                    float bia = gru_bih[o];
                    sgi[0][o] = lo2(a01[j]) + bia;
                    sgi[1][o] = hi2(a01[j]) + bia;
                    sgi[2][o] = lo2(a23[j]) + bia;
                    sgi[3][o] = hi2(a23[j]) + bia;
                }
            }
        }
        __syncthreads();

        // ---- phase B2: gates -> pre-LN hidden ----
#pragma unroll
        for (int ii = 0; ii < 3; ii++) {
            int idx = tid + ii * 256;        // 768 = 4 rows * 192 ch
            int r = idx / 192, ch = idx - r * 192;
            float rg = sigf(sgi[r][ch] + sgh[r][ch]);
            float zg = sigf(sgi[r][192 + ch] + sgh[r][192 + ch]);
            float ng = tanhf(sgi[r][384 + ch] + rg * sgh[r][384 + ch]);
            float hr = sSt[ch][r];
            spre[r][ch] = (1.0f - zg) * ng + zg * hr;
        }
        __syncthreads();

        // ---- phase B3: LN + rho/phi + rotate (warps 0..3, one row each) ----
        if (wid < 4) {
            int r = wid, row = r0 + r;
            float v[6], sum = 0.0f;
#pragma unroll
            for (int j = 0; j < 6; j++) { v[j] = spre[r][j * 32 + lane]; sum += v[j]; }
            sum = warp_sum(sum);
            float mean = sum * (1.0f / H_);
            float var = 0.0f;
#pragma unroll
            for (int j = 0; j < 6; j++) { float d = v[j] - mean; var = fmaf(d, d, var); }
            var = warp_sum(var) * (1.0f / H_);
            float inv = rsqrtf(var + 1e-5f);

            float p0 = 0.0f, p1 = 0.0f;
#pragma unroll
            for (int j = 0; j < 6; j++) {
                int ch = j * 32 + lane;
                float hn = (v[j] - mean) * inv * roll_ln_w[ch] + roll_ln_b[ch];
                sSt[ch][r] = hn;
                p0 = fmaf(hn, fc_rp_r_w[ch], p0);
                p1 = fmaf(hn, fc_rp_r_w[H_ + ch], p1);
            }
            p0 = warp_sum(p0);
            p1 = warp_sum(p1);
            float rho = 1.25f * sigf(p0 + fc_rp_r_b[0]);
            float phi = PI_ * tanhf(p1 + fc_rp_r_b[1]);
            float s, c;
            sincosf(phi, &s, &c);
            float cur = sSt[192 + lane][r];
            float partner = __shfl_xor_sync(0xffffffffu, cur, 16);
            float nv = (lane < 16) ? rho * (c * cur - s * partner)
                                   : rho * (s * partner + c * cur);
            sSt[192 + lane][r] = nv;
            out[((size_t)row * w_out + step) * D_ + lane] = nv;
        }
        __syncthreads();
    }
}

// -----------------------------------------------------------------------------
extern "C" void kernel_launch(void* const* d_in, const int* in_sizes, int n_in,
                              void* d_out, int out_size) {
    const float* x_in      = (const float*)d_in[0];
    const float* inp_w     = (const float*)d_in[1];
    const float* inp_b     = (const float*)d_in[2];
    const float* b_dw_w    = (const float*)d_in[3];
    const float* b_dw_b    = (const float*)d_in[4];
    const float* b_ln_w    = (const float*)d_in[5];
    const float* b_ln_b    = (const float*)d_in[6];
    const float* b_pw1_w   = (const float*)d_in[7];
    const float* b_pw1_b   = (const float*)d_in[8];
    const float* b_grn_g   = (const float*)d_in[9];
    const float* b_grn_b   = (const float*)d_in[10];
    const float* b_pw2_w   = (const float*)d_in[11];
    const float* b_pw2_b   = (const float*)d_in[12];
    const float* out_ln_w  = (const float*)d_in[13];
    const float* out_ln_b  = (const float*)d_in[14];
    const float* fc_rp_w   = (const float*)d_in[15];
    const float* fc_rp_b   = (const float*)d_in[16];
    const float* fc_gain_w = (const float*)d_in[17];
    const float* fc_gain_b = (const float*)d_in[18];
    const float* roll_in_w = (const float*)d_in[19];
    const float* roll_in_b = (const float*)d_in[20];
    const float* gru_wih   = (const float*)d_in[21];
    const float* gru_whh   = (const float*)d_in[22];
    const float* gru_bih   = (const float*)d_in[23];
    const float* gru_bhh   = (const float*)d_in[24];
    const float* roll_ln_w = (const float*)d_in[25];
    const float* roll_ln_b = (const float*)d_in[26];
    const float* fc_rp_r_w = (const float*)d_in[27];
    const float* fc_rp_r_b = (const float*)d_in[28];

    float* out = (float*)d_out;
    const int w_out = out_size / (B_ * D_);

    // 1. input projection with features on the fly: x_in -> g_h(1)
    {
        dim3 grid(H_ / 64, BQ_ / 256);
        k_gemm<3><<<grid, 256>>>(0, 1, inp_w, inp_b, INC_, H_, nullptr, x_in);
    }

    // 2. ConvNeXt blocks
    for (int blk = 0; blk < 2; blk++) {
        {
            dim3 grid(Q_ / 16, B_);
            k_conv<<<grid, 256>>>(b_dw_w + blk * H_ * 9, b_dw_b + blk * H_,
                                  b_ln_w + blk * H_,     b_ln_b + blk * H_);
        }
        {
            // pw1 + GELU + GRN partials: g_y(2) -> g_y1(3)
            dim3 grid(HID_ / 64, BQ_ / 256);
            k_gemm<1><<<grid, 256>>>(2, 3, b_pw1_w + blk * HID_ * H_,
                                     b_pw1_b + blk * HID_, H_, HID_,
                                     nullptr, nullptr);
        }
        k_grn2<<<B_, HID_>>>(b_grn_g + blk * HID_);
        {
            // pw2 + GRN-on-load + residual: g_y1(3) -> g_h(1)
            dim3 grid(H_ / 64, BQ_ / 256);
            k_gemm<2><<<grid, 256>>>(3, 1, b_pw2_w + blk * H_ * HID_,
                                     b_pw2_b + blk * H_, HID_, H_,
                                     b_grn_b + blk * HID_, nullptr);
        }
    }

    // 3. out-LN + rho/phi/gain (+ capture h_seq[:, -1, :])
    k_rpg<<<BQ_ / 8, 256>>>(out_ln_w, out_ln_b, fc_rp_w, fc_rp_b,
                            fc_gain_w, fc_gain_b);

    // 4. Kalman scan -> g_curr
    k_scan<<<B_ / 8, 256>>>(x_in);

    // 5. pack rollout weights
    k_pack<<<(224 * 768 + 768 + 192 * 576 + 255) / 256, 256>>>(
        roll_in_w, roll_in_b, gru_whh, gru_bhh, gru_wih);

    // 6. persistent GRU rollout (single launch)
    k_roll<<<B_ / 4, 256>>>(gru_bih, roll_ln_w, roll_ln_b,
                            fc_rp_r_w, fc_rp_r_b, out, w_out);
}